// round 14
// baseline (speedup 1.0000x reference)
#include <cuda_runtime.h>
#include <cstdint>

__device__ __forceinline__ uint32_t tf32c(float f) {
    uint32_t u; asm("cvt.rna.tf32.f32 %0, %1;" : "=r"(u) : "f"(f)); return u;
}
__device__ __forceinline__ void red2(float* addr, float a, float b) {
    asm volatile("red.global.add.v2.f32 [%0], {%1, %2};"
                 :: "l"(addr), "f"(a), "f"(b) : "memory");
}
// D(16x8) += A(16x8,row) * B(8x8,col)  [tf32, fp32 accum]
__device__ __forceinline__ void mma8(float d[4],
    uint32_t a0, uint32_t a1, uint32_t a2, uint32_t a3, uint32_t b0, uint32_t b1) {
    asm volatile("mma.sync.aligned.m16n8k8.row.col.f32.tf32.tf32.f32 "
        "{%0,%1,%2,%3}, {%4,%5,%6,%7}, {%8,%9}, {%0,%1,%2,%3};"
        : "+f"(d[0]), "+f"(d[1]), "+f"(d[2]), "+f"(d[3])
        : "r"(a0), "r"(a1), "r"(a2), "r"(a3), "r"(b0), "r"(b1));
}

#define BB 16
#define NPIX 1024
#define DD 128
#define KK 32
#define CHUNKS 16
#define ROWS_CTA 64
#define NTHREADS 512
#define STR 132     // XH/XL/CH/CL row stride (u32); cols 128..131 = spare (x2, rowsums)
#define AST 40      // A row stride: conflict-free (8*tig+gid) A-frag loads

// dynamic smem layout (bytes) — total 114176 (~111.5 KB) => 2 CTAs/SM
#define O_XH  0                    // tf32 x-hi [64][132]   33792 (+rowsum spare)
#define O_XL  33792                // tf32 x-lo             33792 (+x2 spare)
#define O_CH  67584                // tf32 c-hi [32][132]   16896 ; AL overlays after logits
#define O_CL  84480                // tf32 c-lo             16896
#define O_AH  101376               // exp f32 -> AH tf32 in place [64][40]  10240
#define O_P1  111616
#define O_P2  111744
#define O_P3  111872
#define O_SKS 112000               // Sk partials [16][32]  2048
#define O_SK  114048               // Sk [32]               128
#define SMEM_TOTAL 114176

__global__ void zero_kernel(float4* out, int n4) {
    int i = blockIdx.x * blockDim.x + threadIdx.x;
    if (i < n4) out[i] = make_float4(0.f, 0.f, 0.f, 0.f);
}

__global__ void __launch_bounds__(NTHREADS, 2) enc_kernel(
    const float* __restrict__ x, const float* __restrict__ cw,
    const float* __restrict__ scale, float* __restrict__ out)
{
    extern __shared__ __align__(16) char sm[];
    uint32_t* XH = (uint32_t*)(sm + O_XH);
    uint32_t* XL = (uint32_t*)(sm + O_XL);
    uint32_t* CH = (uint32_t*)(sm + O_CH);
    uint32_t* CL = (uint32_t*)(sm + O_CL);
    float*    XHf = (float*)(sm + O_XH);     // spare cols: per-(row,ntile) exp sums
    float*    XLf = (float*)(sm + O_XL);     // spare col 128: x2
    float*    Ef  = (float*)(sm + O_AH);     // exp values (pre-normalize)
    uint32_t* AH  = (uint32_t*)(sm + O_AH);  // tf32 hi of A (in place over Ef)
    uint32_t* AL  = (uint32_t*)(sm + O_CH);  // tf32 lo of A (overlays CH)
    float* p1  = (float*)(sm + O_P1);
    float* p2  = (float*)(sm + O_P2);
    float* p3  = (float*)(sm + O_P3);
    float* SkS = (float*)(sm + O_SKS);
    float* Sk  = (float*)(sm + O_SK);

    const int t = threadIdx.x, lane = t & 31, w = t >> 5;   // w: 0..15
    const int gid = lane >> 2, tig = lane & 3;
    const int b = blockIdx.y, chunk = blockIdx.x;

    // ============ stage: x -> XH/XL, c -> CH/CL (tf32 hi/lo); x2/c2 free ============
    {
        const float4* xg = (const float4*)(x + ((size_t)b * NPIX + chunk * ROWS_CTA) * DD);
        const float4* cg = (const float4*)cw;
        float q[4], qc[2];
        #pragma unroll
        for (int p = 0; p < 4; p++) {
            float4 v = xg[p * NTHREADS + t];            // row = 16p + w, col = 4*lane
            int off = (16 * p + w) * STR + 4 * lane;
            uint4 h, l;
            h.x = tf32c(v.x); h.y = tf32c(v.y); h.z = tf32c(v.z); h.w = tf32c(v.w);
            l.x = tf32c(v.x - __uint_as_float(h.x));
            l.y = tf32c(v.y - __uint_as_float(h.y));
            l.z = tf32c(v.z - __uint_as_float(h.z));
            l.w = tf32c(v.w - __uint_as_float(h.w));
            *(uint4*)&XH[off] = h;
            *(uint4*)&XL[off] = l;
            float s = v.x * v.x; s = fmaf(v.y, v.y, s);
            s = fmaf(v.z, v.z, s); q[p] = fmaf(v.w, v.w, s);
        }
        #pragma unroll
        for (int p = 0; p < 2; p++) {
            float4 v = cg[p * NTHREADS + t];            // k = 16p + w, col = 4*lane
            int off = (16 * p + w) * STR + 4 * lane;
            uint4 h, l;
            h.x = tf32c(v.x); h.y = tf32c(v.y); h.z = tf32c(v.z); h.w = tf32c(v.w);
            l.x = tf32c(v.x - __uint_as_float(h.x));
            l.y = tf32c(v.y - __uint_as_float(h.y));
            l.z = tf32c(v.z - __uint_as_float(h.z));
            l.w = tf32c(v.w - __uint_as_float(h.w));
            *(uint4*)&CH[off] = h;
            *(uint4*)&CL[off] = l;
            float s = v.x * v.x; s = fmaf(v.y, v.y, s);
            s = fmaf(v.z, v.z, s); qc[p] = fmaf(v.w, v.w, s);
        }
        #pragma unroll
        for (int off = 16; off > 0; off >>= 1) {
            #pragma unroll
            for (int p = 0; p < 4; p++) q[p] += __shfl_xor_sync(0xffffffffu, q[p], off);
            #pragma unroll
            for (int p = 0; p < 2; p++) qc[p] += __shfl_xor_sync(0xffffffffu, qc[p], off);
        }
        if (lane == 0) {
            #pragma unroll
            for (int p = 0; p < 4; p++) XLf[(16 * p + w) * STR + 128] = q[p];  // x2
            #pragma unroll
            for (int p = 0; p < 2; p++) {
                int k = 16 * p + w;
                float s = scale[k];
                p1[k] = s; p2[k] = -2.f * s; p3[k] = s * qc[p];
            }
        }
    }
    __syncthreads();

    // ====== logits GEMM: warp = (rt: 4 row-tiles of 16, nt: 4 n-tiles of 8 k's) ======
    {
        const int rt = w & 3, nt = w >> 2;
        const int r0 = 16 * rt + gid, r1 = r0 + 8;
        const int kb = 8 * nt + gid;
        float dA[4] = {0,0,0,0}, dB[4] = {0,0,0,0}, dC[4] = {0,0,0,0};
        #pragma unroll
        for (int c = 0; c < 16; c++) {
            const int cb = c * 8;
            uint32_t ah0 = XH[r0 * STR + cb + tig],     ah1 = XH[r1 * STR + cb + tig];
            uint32_t ah2 = XH[r0 * STR + cb + tig + 4], ah3 = XH[r1 * STR + cb + tig + 4];
            uint32_t al0 = XL[r0 * STR + cb + tig],     al1 = XL[r1 * STR + cb + tig];
            uint32_t al2 = XL[r0 * STR + cb + tig + 4], al3 = XL[r1 * STR + cb + tig + 4];
            uint32_t bh0 = CH[kb * STR + cb + tig], bh1 = CH[kb * STR + cb + tig + 4];
            uint32_t bl0 = CL[kb * STR + cb + tig], bl1 = CL[kb * STR + cb + tig + 4];
            mma8(dA, ah0, ah1, ah2, ah3, bh0, bh1);
            mma8(dB, ah0, ah1, ah2, ah3, bl0, bl1);
            mma8(dC, al0, al1, al2, al3, bh0, bh1);
        }
        float d[4];
        #pragma unroll
        for (int j = 0; j < 4; j++) d[j] = (dA[j] + dB[j]) + dC[j];

        // exp + quarter-row sums (no max-subtraction: scale<0, logits bounded;
        // validated rel_err ~2.5e-7 across many rounds)
        const float x20 = XLf[r0 * STR + 128], x21 = XLf[r1 * STR + 128];
        float s0 = 0.f, s1 = 0.f;
        #pragma unroll
        for (int p = 0; p < 2; p++) {
            int k = 8 * nt + 2 * tig + p;
            float P1 = p1[k], P2 = p2[k], P3 = p3[k];
            float e0 = __expf(fmaf(P1, x20, fmaf(P2, d[p],     P3)));
            float e1 = __expf(fmaf(P1, x21, fmaf(P2, d[2 + p], P3)));
            Ef[r0 * AST + k] = e0;
            Ef[r1 * AST + k] = e1;
            s0 += e0; s1 += e1;
        }
        s0 += __shfl_xor_sync(0xffffffffu, s0, 1);
        s0 += __shfl_xor_sync(0xffffffffu, s0, 2);
        s1 += __shfl_xor_sync(0xffffffffu, s1, 1);
        s1 += __shfl_xor_sync(0xffffffffu, s1, 2);
        if (tig == 0) {
            XHf[r0 * STR + 128 + nt] = s0;   // spare cols of XH hold quarter sums
            XHf[r1 * STR + 128 + nt] = s1;
        }
    }
    __syncthreads();

    // ==== normalize + split A to AH/AL (AL overlays CH — dead now) + Sk partials ====
    {
        float skp = 0.f;
        #pragma unroll
        for (int j = 0; j < 4; j++) {
            int r = 4 * w + j;
            float rs = (XHf[r * STR + 128] + XHf[r * STR + 129])
                     + (XHf[r * STR + 130] + XHf[r * STR + 131]);
            float a = Ef[r * AST + lane] * __fdividef(1.f, rs);
            uint32_t hi = tf32c(a);
            AH[r * AST + lane] = hi;                         // in place over Ef
            AL[r * AST + lane] = tf32c(a - __uint_as_float(hi));
            skp += a;
        }
        SkS[w * 32 + lane] = skp;
    }
    __syncthreads();
    if (w == 0) {
        float s = 0.f;
        #pragma unroll
        for (int i = 0; i < 16; i++) s += SkS[i * 32 + lane];
        Sk[lane] = s;
    }
    __syncthreads();

    // ========== E GEMM: D[kk][d] = sum_r A[r][kk] * X[r][d], 3xTF32 mma ==========
    // warp = (mt = w>>3: kk-tile of 16, ng = w&7: d-group of 16); 8 k-steps
    {
        const int mt = w >> 3, ng = w & 7;
        const int kk0 = 16 * mt + gid;
        const int d0c = 16 * ng + gid;
        float fA[4] = {0,0,0,0}, fB[4] = {0,0,0,0}, fC[4] = {0,0,0,0};
        float gA[4] = {0,0,0,0}, gB[4] = {0,0,0,0}, gC[4] = {0,0,0,0};
        #pragma unroll
        for (int s = 0; s < 8; s++) {
            const int rb = 8 * s;
            uint32_t ah0 = AH[(rb + tig) * AST + kk0];
            uint32_t ah1 = AH[(rb + tig) * AST + kk0 + 8];
            uint32_t ah2 = AH[(rb + tig + 4) * AST + kk0];
            uint32_t ah3 = AH[(rb + tig + 4) * AST + kk0 + 8];
            uint32_t al0 = AL[(rb + tig) * AST + kk0];
            uint32_t al1 = AL[(rb + tig) * AST + kk0 + 8];
            uint32_t al2 = AL[(rb + tig + 4) * AST + kk0];
            uint32_t al3 = AL[(rb + tig + 4) * AST + kk0 + 8];
            uint32_t bh0 = XH[(rb + tig) * STR + d0c], bh1 = XH[(rb + tig + 4) * STR + d0c];
            uint32_t bl0 = XL[(rb + tig) * STR + d0c], bl1 = XL[(rb + tig + 4) * STR + d0c];
            mma8(fA, ah0, ah1, ah2, ah3, bh0, bh1);
            mma8(fB, ah0, ah1, ah2, ah3, bl0, bl1);
            mma8(fC, al0, al1, al2, al3, bh0, bh1);
            bh0 = XH[(rb + tig) * STR + d0c + 8]; bh1 = XH[(rb + tig + 4) * STR + d0c + 8];
            bl0 = XL[(rb + tig) * STR + d0c + 8]; bl1 = XL[(rb + tig + 4) * STR + d0c + 8];
            mma8(gA, ah0, ah1, ah2, ah3, bh0, bh1);
            mma8(gB, ah0, ah1, ah2, ah3, bl0, bl1);
            mma8(gC, al0, al1, al2, al3, bh0, bh1);
        }
        float v0[4], v1[4];
        #pragma unroll
        for (int j = 0; j < 4; j++) {
            v0[j] = (fA[j] + fB[j]) + fC[j];
            v1[j] = (gA[j] + gB[j]) + gC[j];
        }
        const float sk0 = Sk[kk0], sk1 = Sk[kk0 + 8];
        const int dd = 16 * ng + 2 * tig;
        const float* cb0 = cw + (size_t)kk0 * DD;
        const float* cb1 = cw + (size_t)(kk0 + 8) * DD;
        float* ob0 = out + ((size_t)(b * KK + kk0)) * DD;
        float* ob1 = out + ((size_t)(b * KK + kk0 + 8)) * DD;
        float2 c00 = *(const float2*)&cb0[dd];
        float2 c01 = *(const float2*)&cb0[dd + 8];
        float2 c10 = *(const float2*)&cb1[dd];
        float2 c11 = *(const float2*)&cb1[dd + 8];
        red2(&ob0[dd],     fmaf(-sk0, c00.x, v0[0]), fmaf(-sk0, c00.y, v0[1]));
        red2(&ob0[dd + 8], fmaf(-sk0, c01.x, v1[0]), fmaf(-sk0, c01.y, v1[1]));
        red2(&ob1[dd],     fmaf(-sk1, c10.x, v0[2]), fmaf(-sk1, c10.y, v0[3]));
        red2(&ob1[dd + 8], fmaf(-sk1, c11.x, v1[2]), fmaf(-sk1, c11.y, v1[3]));
    }
}

extern "C" void kernel_launch(void* const* d_in, const int* in_sizes, int n_in,
                              void* d_out, int out_size) {
    const float* x  = (const float*)d_in[0];
    const float* cw = (const float*)d_in[1];
    const float* sc = (const float*)d_in[2];
    float* out = (float*)d_out;

    cudaFuncSetAttribute(enc_kernel, cudaFuncAttributeMaxDynamicSharedMemorySize, SMEM_TOTAL);
    cudaFuncSetAttribute(enc_kernel, cudaFuncAttributePreferredSharedMemoryCarveout, 100);

    int n4 = out_size / 4;
    zero_kernel<<<(n4 + 255) / 256, 256>>>((float4*)out, n4);

    dim3 grid(CHUNKS, BB);
    enc_kernel<<<grid, NTHREADS, SMEM_TOTAL>>>(x, cw, sc, out);
}

// round 15
// speedup vs baseline: 1.2931x; 1.2931x over previous
#include <cuda_runtime.h>
#include <cstdint>

__device__ __forceinline__ uint32_t tf32c(float f) {
    uint32_t u; asm("cvt.rna.tf32.f32 %0, %1;" : "=r"(u) : "f"(f)); return u;
}
__device__ __forceinline__ void red2(float* addr, float a, float b) {
    asm volatile("red.global.add.v2.f32 [%0], {%1, %2};"
                 :: "l"(addr), "f"(a), "f"(b) : "memory");
}
// D(16x8) += A(16x8,row) * B(8x8,col)  [tf32, fp32 accum]
__device__ __forceinline__ void mma8(float d[4],
    uint32_t a0, uint32_t a1, uint32_t a2, uint32_t a3, uint32_t b0, uint32_t b1) {
    asm volatile("mma.sync.aligned.m16n8k8.row.col.f32.tf32.tf32.f32 "
        "{%0,%1,%2,%3}, {%4,%5,%6,%7}, {%8,%9}, {%0,%1,%2,%3};"
        : "+f"(d[0]), "+f"(d[1]), "+f"(d[2]), "+f"(d[3])
        : "r"(a0), "r"(a1), "r"(a2), "r"(a3), "r"(b0), "r"(b1));
}

#define BB 16
#define NPIX 1024
#define DD 128
#define KK 32
#define CHUNKS 8
#define ROWS_CTA 128
#define NTHREADS 512
#define STR 132     // XH/XL/CH/CL row stride (u32): conflict-free (4g+t) frag loads
#define AST 40      // A row stride (floats/u32): conflict-free A-frag loads

// dynamic smem layout (bytes)
#define O_XH  0                          // tf32 x-hi [128][132] u32   67584
#define O_XL  67584                      // tf32 x-lo                  67584
#define O_CH  135168                     // tf32 c-hi [32][132]        16896  -> AL overlay after logits
#define O_CL  152064                     // tf32 c-lo                  16896
#define O_AS  168960                     // exp f32 -> AH tf32 in place [128][40]  20480
#define O_X2  189440                     // x2 [128]                   512
#define O_PS  189952                     // half-row exp sums [128][2] 1024
#define O_P1  190976
#define O_P2  191104
#define O_P3  191232
#define O_SKS 191360                     // Sk partials [16][32]       2048
#define O_SK  193408                     // Sk [32]                    128
#define SMEM_TOTAL 193536

__global__ void zero_kernel(float4* out, int n4) {
    int i = blockIdx.x * blockDim.x + threadIdx.x;
    if (i < n4) out[i] = make_float4(0.f, 0.f, 0.f, 0.f);
}

__global__ void __launch_bounds__(NTHREADS) enc_kernel(
    const float* __restrict__ x, const float* __restrict__ cw,
    const float* __restrict__ scale, float* __restrict__ out)
{
    extern __shared__ __align__(16) char sm[];
    uint32_t* XH = (uint32_t*)(sm + O_XH);
    uint32_t* XL = (uint32_t*)(sm + O_XL);
    uint32_t* CH = (uint32_t*)(sm + O_CH);
    uint32_t* CL = (uint32_t*)(sm + O_CL);
    float*    Ef = (float*)(sm + O_AS);      // exp values (pre-normalize)
    uint32_t* AH = (uint32_t*)(sm + O_AS);   // tf32-hi of A, in place over Ef
    uint32_t* AL = (uint32_t*)(sm + O_CH);   // tf32-lo of A, overlays dead CH
    float* x2s = (float*)(sm + O_X2);
    float* ps  = (float*)(sm + O_PS);
    float* p1  = (float*)(sm + O_P1);
    float* p2  = (float*)(sm + O_P2);
    float* p3  = (float*)(sm + O_P3);
    float* SkS = (float*)(sm + O_SKS);
    float* Sk  = (float*)(sm + O_SK);

    const int t = threadIdx.x, lane = t & 31, w = t >> 5;   // w: 0..15
    const int gid = lane >> 2, tig = lane & 3;
    const int b = blockIdx.y, chunk = blockIdx.x;

    // ================= stage: x -> XH/XL (tf32 hi/lo), c -> CH/CL; x2/c2 free =================
    {
        const float4* xg = (const float4*)(x + ((size_t)b * NPIX + chunk * ROWS_CTA) * DD);
        const float4* cg = (const float4*)cw;
        float q[8], qc[2];
        #pragma unroll
        for (int p = 0; p < 8; p++) {
            float4 v = xg[p * NTHREADS + t];            // row = 16p + w, col = 4*lane
            int off = (16 * p + w) * STR + 4 * lane;
            uint4 h, l;
            h.x = tf32c(v.x); h.y = tf32c(v.y); h.z = tf32c(v.z); h.w = tf32c(v.w);
            l.x = tf32c(v.x - __uint_as_float(h.x));
            l.y = tf32c(v.y - __uint_as_float(h.y));
            l.z = tf32c(v.z - __uint_as_float(h.z));
            l.w = tf32c(v.w - __uint_as_float(h.w));
            *(uint4*)&XH[off] = h;
            *(uint4*)&XL[off] = l;
            float s = v.x * v.x; s = fmaf(v.y, v.y, s);
            s = fmaf(v.z, v.z, s); q[p] = fmaf(v.w, v.w, s);
        }
        #pragma unroll
        for (int p = 0; p < 2; p++) {
            float4 v = cg[p * NTHREADS + t];            // k = 16p + w, col = 4*lane
            int off = (16 * p + w) * STR + 4 * lane;
            uint4 h, l;
            h.x = tf32c(v.x); h.y = tf32c(v.y); h.z = tf32c(v.z); h.w = tf32c(v.w);
            l.x = tf32c(v.x - __uint_as_float(h.x));
            l.y = tf32c(v.y - __uint_as_float(h.y));
            l.z = tf32c(v.z - __uint_as_float(h.z));
            l.w = tf32c(v.w - __uint_as_float(h.w));
            *(uint4*)&CH[off] = h;
            *(uint4*)&CL[off] = l;
            float s = v.x * v.x; s = fmaf(v.y, v.y, s);
            s = fmaf(v.z, v.z, s); qc[p] = fmaf(v.w, v.w, s);
        }
        #pragma unroll
        for (int off = 16; off > 0; off >>= 1) {
            #pragma unroll
            for (int p = 0; p < 8; p++) q[p] += __shfl_xor_sync(0xffffffffu, q[p], off);
            #pragma unroll
            for (int p = 0; p < 2; p++) qc[p] += __shfl_xor_sync(0xffffffffu, qc[p], off);
        }
        if (lane == 0) {
            #pragma unroll
            for (int p = 0; p < 8; p++) x2s[16 * p + w] = q[p];
            #pragma unroll
            for (int p = 0; p < 2; p++) {
                int k = 16 * p + w;
                float s = scale[k];
                p1[k] = s; p2[k] = -2.f * s; p3[k] = s * qc[p];
            }
        }
    }
    __syncthreads();

    // ========== logits GEMM: 3xTF32 mma; warp = (rt row-tile, nth k-half) ==========
    {
        const int rt = w & 7, nth = w >> 3;
        const int r0 = 16 * rt + gid, r1 = r0 + 8;
        const int kb0 = 16 * nth + gid, kb1 = kb0 + 8;
        float dA[4] = {0,0,0,0}, dB[4] = {0,0,0,0}, dC[4] = {0,0,0,0};
        float eA[4] = {0,0,0,0}, eB[4] = {0,0,0,0}, eC[4] = {0,0,0,0};
        #pragma unroll
        for (int c = 0; c < 16; c++) {
            const int cb = c * 8;
            uint32_t ah0 = XH[r0 * STR + cb + tig],     ah1 = XH[r1 * STR + cb + tig];
            uint32_t ah2 = XH[r0 * STR + cb + tig + 4], ah3 = XH[r1 * STR + cb + tig + 4];
            uint32_t al0 = XL[r0 * STR + cb + tig],     al1 = XL[r1 * STR + cb + tig];
            uint32_t al2 = XL[r0 * STR + cb + tig + 4], al3 = XL[r1 * STR + cb + tig + 4];
            uint32_t bh0 = CH[kb0 * STR + cb + tig], bh1 = CH[kb0 * STR + cb + tig + 4];
            uint32_t bl0 = CL[kb0 * STR + cb + tig], bl1 = CL[kb0 * STR + cb + tig + 4];
            mma8(dA, ah0, ah1, ah2, ah3, bh0, bh1);
            mma8(dB, ah0, ah1, ah2, ah3, bl0, bl1);
            mma8(dC, al0, al1, al2, al3, bh0, bh1);
            bh0 = CH[kb1 * STR + cb + tig]; bh1 = CH[kb1 * STR + cb + tig + 4];
            bl0 = CL[kb1 * STR + cb + tig]; bl1 = CL[kb1 * STR + cb + tig + 4];
            mma8(eA, ah0, ah1, ah2, ah3, bh0, bh1);
            mma8(eB, ah0, ah1, ah2, ah3, bl0, bl1);
            mma8(eC, al0, al1, al2, al3, bh0, bh1);
        }
        float d0[4], d1[4];
        #pragma unroll
        for (int j = 0; j < 4; j++) {
            d0[j] = (dA[j] + dB[j]) + dC[j];
            d1[j] = (eA[j] + eB[j]) + eC[j];
        }
        // exp + half-row sums (no max-subtraction: scale<0, logits bounded;
        // validated rel_err ~2.5e-7 across rounds)
        const float x20 = x2s[r0], x21 = x2s[r1];
        float s0 = 0.f, s1 = 0.f;
        #pragma unroll
        for (int tt = 0; tt < 2; tt++) {
            const float* D = tt ? d1 : d0;
            #pragma unroll
            for (int p = 0; p < 2; p++) {
                int k = 16 * nth + 8 * tt + 2 * tig + p;
                float P1 = p1[k], P2 = p2[k], P3 = p3[k];
                float e0 = __expf(fmaf(P1, x20, fmaf(P2, D[p],     P3)));
                float e1 = __expf(fmaf(P1, x21, fmaf(P2, D[2 + p], P3)));
                Ef[r0 * AST + k] = e0;
                Ef[r1 * AST + k] = e1;
                s0 += e0; s1 += e1;
            }
        }
        s0 += __shfl_xor_sync(0xffffffffu, s0, 1);
        s0 += __shfl_xor_sync(0xffffffffu, s0, 2);
        s1 += __shfl_xor_sync(0xffffffffu, s1, 1);
        s1 += __shfl_xor_sync(0xffffffffu, s1, 2);
        if (tig == 0) { ps[r0 * 2 + nth] = s0; ps[r1 * 2 + nth] = s1; }
    }
    __syncthreads();

    // ==== normalize + split A -> AH (in place) / AL (over dead CH) + Sk partials ====
    {
        float skp = 0.f;
        #pragma unroll
        for (int j = 0; j < 8; j++) {
            int r = 16 * j + w;
            float rinv = __fdividef(1.f, ps[2 * r] + ps[2 * r + 1]);
            float a = Ef[r * AST + lane] * rinv;
            uint32_t hi = tf32c(a);
            AH[r * AST + lane] = hi;
            AL[r * AST + lane] = tf32c(a - __uint_as_float(hi));
            skp += a;
        }
        SkS[w * 32 + lane] = skp;
    }
    __syncthreads();
    if (w == 0) {
        float s = 0.f;
        #pragma unroll
        for (int i = 0; i < 16; i++) s += SkS[i * 32 + lane];
        Sk[lane] = s;
    }
    __syncthreads();

    // ========== E GEMM: D[kk][d] = sum_r A[r][kk] * X[r][d], 3xTF32 mma ==========
    // warp = (mt = w>>3: kk-tile of 16, ng = w&7: d-group of 16)
    {
        const int mt = w >> 3, ng = w & 7;
        const int kk0 = 16 * mt + gid;           // A m-rows: kk0, kk0+8
        const int d0c = 16 * ng + gid;           // B n-cols: d0c (tile0), d0c+8 (tile1)
        float fA[4] = {0,0,0,0}, fB[4] = {0,0,0,0}, fC[4] = {0,0,0,0};
        float gA[4] = {0,0,0,0}, gB[4] = {0,0,0,0}, gC[4] = {0,0,0,0};
        #pragma unroll
        for (int s = 0; s < 16; s++) {
            const int rb = 8 * s;
            // A fragment: precomputed hi/lo, plain LDS
            uint32_t ah0 = AH[(rb + tig) * AST + kk0];
            uint32_t ah1 = AH[(rb + tig) * AST + kk0 + 8];
            uint32_t ah2 = AH[(rb + tig + 4) * AST + kk0];
            uint32_t ah3 = AH[(rb + tig + 4) * AST + kk0 + 8];
            uint32_t al0 = AL[(rb + tig) * AST + kk0];
            uint32_t al1 = AL[(rb + tig) * AST + kk0 + 8];
            uint32_t al2 = AL[(rb + tig + 4) * AST + kk0];
            uint32_t al3 = AL[(rb + tig + 4) * AST + kk0 + 8];
            // B fragment: B[k=r][n=d] = X[r][d] (col-major thread map)
            uint32_t bh0 = XH[(rb + tig) * STR + d0c],     bh1 = XH[(rb + tig + 4) * STR + d0c];
            uint32_t bl0 = XL[(rb + tig) * STR + d0c],     bl1 = XL[(rb + tig + 4) * STR + d0c];
            mma8(fA, ah0, ah1, ah2, ah3, bh0, bh1);
            mma8(fB, ah0, ah1, ah2, ah3, bl0, bl1);
            mma8(fC, al0, al1, al2, al3, bh0, bh1);
            bh0 = XH[(rb + tig) * STR + d0c + 8]; bh1 = XH[(rb + tig + 4) * STR + d0c + 8];
            bl0 = XL[(rb + tig) * STR + d0c + 8]; bl1 = XL[(rb + tig + 4) * STR + d0c + 8];
            mma8(gA, ah0, ah1, ah2, ah3, bh0, bh1);
            mma8(gB, ah0, ah1, ah2, ah3, bl0, bl1);
            mma8(gC, al0, al1, al2, al3, bh0, bh1);
        }
        // combine + epilogue: out[(b*32+kk)*128+d] += D - Sk[kk]*c[kk][d]
        float v0[4], v1[4];
        #pragma unroll
        for (int j = 0; j < 4; j++) {
            v0[j] = (fA[j] + fB[j]) + fC[j];   // n-tile0: d = 16ng+2tig(+1)
            v1[j] = (gA[j] + gB[j]) + gC[j];   // n-tile1: d = 16ng+8+2tig(+1)
        }
        const float sk0 = Sk[kk0], sk1 = Sk[kk0 + 8];
        const int dd = 16 * ng + 2 * tig;
        const float* cb0 = cw + (size_t)kk0 * DD;
        const float* cb1 = cw + (size_t)(kk0 + 8) * DD;
        float* ob0 = out + ((size_t)(b * KK + kk0)) * DD;
        float* ob1 = out + ((size_t)(b * KK + kk0 + 8)) * DD;
        float2 c00 = *(const float2*)&cb0[dd];
        float2 c01 = *(const float2*)&cb0[dd + 8];
        float2 c10 = *(const float2*)&cb1[dd];
        float2 c11 = *(const float2*)&cb1[dd + 8];
        red2(&ob0[dd],     fmaf(-sk0, c00.x, v0[0]), fmaf(-sk0, c00.y, v0[1]));
        red2(&ob0[dd + 8], fmaf(-sk0, c01.x, v1[0]), fmaf(-sk0, c01.y, v1[1]));
        red2(&ob1[dd],     fmaf(-sk1, c10.x, v0[2]), fmaf(-sk1, c10.y, v0[3]));
        red2(&ob1[dd + 8], fmaf(-sk1, c11.x, v1[2]), fmaf(-sk1, c11.y, v1[3]));
    }
}

extern "C" void kernel_launch(void* const* d_in, const int* in_sizes, int n_in,
                              void* d_out, int out_size) {
    const float* x  = (const float*)d_in[0];
    const float* cw = (const float*)d_in[1];
    const float* sc = (const float*)d_in[2];
    float* out = (float*)d_out;

    cudaFuncSetAttribute(enc_kernel, cudaFuncAttributeMaxDynamicSharedMemorySize, SMEM_TOTAL);

    int n4 = out_size / 4;
    zero_kernel<<<(n4 + 255) / 256, 256>>>((float4*)out, n4);

    dim3 grid(CHUNKS, BB);
    enc_kernel<<<grid, NTHREADS, SMEM_TOTAL>>>(x, cw, sc, out);
}